// round 15
// baseline (speedup 1.0000x reference)
#include <cuda_runtime.h>
#include <cuda_fp16.h>

// GaussianWarpingScheme on GB300 — round 15.
// Pass 1: transpose im (B,C,H,W) f32 -> scratch (B,H,W,C) fp16 (LTS-capped).
// Pass 2: 4 lanes per pixel = (xsel, csel). Each lane 2x LDG.128 covering
//   8 channels of one x-tap for rows y0/y1 -> the 64B x-pair is ~1 line
//   => gather replay-wavefronts 4 -> 2.5 per pixel. Cross-x combine via
//   SHFL.BFLY (no smem, no barriers). Lane pair splits the 8-channel store.

#define Bn 8
#define Cn 16
#define Hn 256
#define Wn 256
#define HWn (Hn * Wn)

__device__ __half g_imH[(size_t)Bn * HWn * Cn];   // 32 MB channel-last scratch

// ---- packed f32x2 helpers ----
__device__ __forceinline__ unsigned long long f2pack(float lo, float hi) {
    unsigned long long r;
    asm("mov.b64 %0,{%1,%2};" : "=l"(r) : "f"(lo), "f"(hi));
    return r;
}
__device__ __forceinline__ unsigned long long h2f2(unsigned int h2) {
    const float2 f = __half22float2(*(const __half2*)&h2);
    return f2pack(f.x, f.y);
}
__device__ __forceinline__ unsigned long long fma2(unsigned long long a,
                                                   unsigned long long b,
                                                   unsigned long long c) {
    unsigned long long d;
    asm("fma.rn.f32x2 %0,%1,%2,%3;" : "=l"(d) : "l"(a), "l"(b), "l"(c));
    return d;
}
__device__ __forceinline__ unsigned long long mul2(unsigned long long a,
                                                   unsigned long long b) {
    unsigned long long d;
    asm("mul.rn.f32x2 %0,%1,%2;" : "=l"(d) : "l"(a), "l"(b));
    return d;
}
__device__ __forceinline__ unsigned long long add2(unsigned long long a,
                                                   unsigned long long b) {
    unsigned long long d;
    asm("add.rn.f32x2 %0,%1,%2;" : "=l"(d) : "l"(a), "l"(b));
    return d;
}
__device__ __forceinline__ float2 f2unpack(unsigned long long a) {
    float2 f;
    asm("mov.b64 {%0,%1},%2;" : "=f"(f.x), "=f"(f.y) : "l"(a));
    return f;
}

// ---------------- Pass 1: (B,C,H,W) f32 -> (B,H,W,C) fp16 ----------------
__global__ void __launch_bounds__(256)
transpose_chw_hwc(const float* __restrict__ im)
{
    const int bh = blockIdx.x;          // 0 .. B*H-1
    const int b  = bh >> 8;
    const int h  = bh & (Hn - 1);
    const int wv = threadIdx.x;

    const float* src = im + ((size_t)(b * Cn) * Hn + h) * Wn + wv;
    __half* dst = g_imH + ((size_t)((b << 8) + h) * Wn + wv) * Cn;

    __half hv[Cn];
#pragma unroll
    for (int c = 0; c < Cn; c++)
        hv[c] = __float2half_rn(src[(size_t)c * HWn]);

    *(uint4*)(dst)     = *(const uint4*)(hv);
    *(uint4*)(dst + 8) = *(const uint4*)(hv + 8);
}

// ---------------- Pass 2: 4 lanes/pixel, shuffle combine ----------------
__global__ void __launch_bounds__(256)
gauss_warp_main(const float* __restrict__ w,
                float* __restrict__ out)
{
    const unsigned FULL = 0xffffffffu;
    const int tid  = threadIdx.x;
    const int xsel = tid & 1;                     // x tap of the pair
    const int csel = (tid >> 1) & 1;              // channel half (0..7 / 8..15)

    const int p   = blockIdx.x * 64 + (tid >> 2); // one pixel per lane-quad
    const int b   = p >> 16;
    const int rem = p & (HWn - 1);
    const int ho  = rem >> 8;
    const int wo  = rem & (Wn - 1);

    // ---- per-pixel params (4 lanes duplicate; SIMT dedups instr cost) ----
    const float w0 = w[b * 2 * HWn + rem];
    const float w1 = w[b * 2 * HWn + HWn + rem];

    const float bx = -1.0f + (float)wo * (2.0f / 255.0f);
    const float by = -1.0f + (float)ho * (2.0f / 255.0f);
    const float x = ((bx - w0) + 1.0f) * 0.5f * 255.0f;
    const float y = ((by - w1) + 1.0f) * 0.5f * 255.0f;
    const int ix = (int)floorf(x);
    const int iy = (int)floorf(y);
    const float fx = x - (float)ix;
    const float fy = y - (float)iy;

    const float wx0m = (ix     >= 0 && ix     < Wn) ? __expf(-8.0f * fx * fx)               : 0.0f;
    const float wx1m = (ix + 1 >= 0 && ix + 1 < Wn) ? __expf(-8.0f * (1.0f-fx) * (1.0f-fx)) : 0.0f;
    const float wy0m = (iy     >= 0 && iy     < Hn) ? __expf(-8.0f * fy * fy)               : 0.0f;
    const float wy1m = (iy + 1 >= 0 && iy + 1 < Hn) ? __expf(-8.0f * (1.0f-fy) * (1.0f-fy)) : 0.0f;

    // x-pair base with boundary-correct slot weights
    const int xb = min(max(ix, 0), Wn - 2);
    float pw0 = 0.0f, pw1 = 0.0f;
    if (ix     == xb)     pw0 += wx0m;
    if (ix + 1 == xb)     pw0 += wx1m;            // ix = -1
    if (ix     == xb + 1) pw1 += wx0m;            // ix = 255
    if (ix + 1 == xb + 1) pw1 += wx1m;

    const int y0 = min(max(iy,     0), Hn - 1);
    const int y1 = min(max(iy + 1, 0), Hn - 1);

    // this lane's x-tap weight for rows y0 / y1
    const float wx  = xsel ? pw1 : pw0;
    const unsigned long long Wt0 = f2pack(wx * wy0m, wx * wy0m);
    const unsigned long long Wt1 = f2pack(wx * wy1m, wx * wy1m);

    // ---- gathers: 2x LDG.128; quad covers the 64B x-pair per row ----
    const __half* bh = g_imH + (size_t)b * HWn * Cn;
    const size_t lo  = (size_t)(xb + xsel) * Cn + csel * 8;

    const uint4 r0 = __ldg((const uint4*)(bh + ((size_t)(y0 << 8) * Cn) + lo));
    const uint4 r1 = __ldg((const uint4*)(bh + ((size_t)(y1 << 8) * Cn) + lo));

    // ---- accumulate own x-tap (8 channels = 4 f32x2) ----
    unsigned long long s0 = mul2(Wt0, h2f2(r0.x));
    unsigned long long s1 = mul2(Wt0, h2f2(r0.y));
    unsigned long long s2 = mul2(Wt0, h2f2(r0.z));
    unsigned long long s3 = mul2(Wt0, h2f2(r0.w));
    s0 = fma2(Wt1, h2f2(r1.x), s0);
    s1 = fma2(Wt1, h2f2(r1.y), s1);
    s2 = fma2(Wt1, h2f2(r1.z), s2);
    s3 = fma2(Wt1, h2f2(r1.w), s3);

    // ---- cross-x combine via butterfly shuffle (partner = lane^1) ----
    s0 = add2(s0, __shfl_xor_sync(FULL, s0, 1));
    s1 = add2(s1, __shfl_xor_sync(FULL, s1, 1));
    s2 = add2(s2, __shfl_xor_sync(FULL, s2, 1));
    s3 = add2(s3, __shfl_xor_sync(FULL, s3, 1));

    // ---- stores: lane pair splits the 8 channels (4 each, no redundancy) --
    // xsel=0 stores channels csel*8+0..3 (s0,s1); xsel=1 stores +4..7 (s2,s3)
    const float2 fa = f2unpack(xsel ? s2 : s0);
    const float2 fb = f2unpack(xsel ? s3 : s1);

    float* op = out + (size_t)b * Cn * HWn
                    + (size_t)(csel * 8 + xsel * 4) * HWn + rem;
    op[0 * HWn] = fa.x;
    op[1 * HWn] = fa.y;
    op[2 * HWn] = fb.x;
    op[3 * HWn] = fb.y;
}

extern "C" void kernel_launch(void* const* d_in, const int* in_sizes, int n_in,
                              void* d_out, int out_size)
{
    const float* im = (const float*)d_in[0];
    const float* w  = (const float*)d_in[1];
    if (n_in >= 2 && in_sizes[0] == Bn * 2 * HWn && in_sizes[1] == Bn * Cn * HWn) {
        im = (const float*)d_in[1];
        w  = (const float*)d_in[0];
    }
    float* out = (float*)d_out;

    transpose_chw_hwc<<<Bn * Hn, 256>>>(im);
    gauss_warp_main<<<(Bn * HWn) / 64, 256>>>(w, out);
}